// round 5
// baseline (speedup 1.0000x reference)
#include <cuda_runtime.h>

#define NB   4
#define NH   4
#define NN   2048
#define FIN  128
#define ND   32
#define BHD  (NB*NH)
#define NCH  16      // chunks per (b,h)
#define CHSZ 128     // rows per chunk

// scratch (device globals; no allocation allowed)
__device__ float  g_xT  [NB*FIN*NN];     // transposed x: [b][k][n]
__device__ float  g_Wh  [BHD*NN*ND];
__device__ float  g_Wh1 [BHD*NN];
__device__ float  g_Wh2 [BHD*NN];
__device__ int    g_perm[BHD*NN];        // sorted pos -> original row
__device__ float  g_w2s [BHD*NN];        // sorted w2 keys
__device__ float  g_SnegL[BHD*NN*ND];    // per-chunk exclusive prefix of exp(.2 w2)*Wh
__device__ float  g_SposL[BHD*NN*ND];    // per-chunk inclusive suffix of exp(w2)*Wh
__device__ float  g_CnegT[BHD*NCH*ND];   // chunk total vectors
__device__ float  g_CposT[BHD*NCH*ND];
__device__ float  g_pnL[BHD*NN];         // scalar local prefix/suffix
__device__ float  g_ppL[BHD*NN];
__device__ float  g_pnT[BHD*NCH];        // scalar chunk totals
__device__ float  g_ppT[BHD*NCH];

__device__ __forceinline__ float warp_incl_scan(float v, int lane) {
    #pragma unroll
    for (int o = 1; o < 32; o <<= 1) {
        float u = __shfl_up_sync(0xffffffffu, v, o);
        if (lane >= o) v += u;
    }
    return v;
}

__device__ __forceinline__ unsigned long long pack2(float x, float y) {
    unsigned long long r;
    asm("mov.b64 %0, {%1, %2};" : "=l"(r) : "f"(x), "f"(y));
    return r;
}
__device__ __forceinline__ float2 unpack2(unsigned long long v) {
    float2 r;
    asm("mov.b64 {%0, %1}, %2;" : "=f"(r.x), "=f"(r.y) : "l"(v));
    return r;
}
__device__ __forceinline__ void ffma2(unsigned long long& d, unsigned long long a, unsigned long long b) {
    asm("fma.rn.f32x2 %0, %1, %2, %0;" : "+l"(d) : "l"(a), "l"(b));
}

// ---------------- kernel 0: transpose x -> xT ----------------
__global__ void __launch_bounds__(256) k0t(const float* __restrict__ x) {
    __shared__ float t[32][33];
    const int b = blockIdx.z, k0 = blockIdx.y * 32, n0 = blockIdx.x * 32;
    const int tx = threadIdx.x, ty = threadIdx.y;   // 32 x 8
    #pragma unroll
    for (int i = 0; i < 4; i++)
        t[ty + i*8][tx] = x[((size_t)b*NN + n0 + ty + i*8)*FIN + k0 + tx];
    __syncthreads();
    #pragma unroll
    for (int i = 0; i < 4; i++)
        g_xT[((size_t)b*FIN + k0 + ty + i*8)*NN + n0 + tx] = t[tx][ty + i*8];
}

// ---------------- kernel 1: Wh = x @ W[h] (register-tiled, f32x2) ----------------
#define SM1_XT    (FIN*132*4)              // xTs floats [128][132]
#define SM1_WS2   (FIN*ND*8)               // Ws2 ull [128][32]
#define SM1_BYTES (SM1_XT + SM1_WS2 + 256)

__global__ void __launch_bounds__(256) k1(const float* __restrict__ W,
                                          const float* __restrict__ a) {
    extern __shared__ char sm1[];
    float (*xTs)[132] = (float(*)[132])sm1;
    unsigned long long (*Ws2)[ND] = (unsigned long long(*)[ND])(sm1 + SM1_XT);
    float* a1s = (float*)(sm1 + SM1_XT + SM1_WS2);
    float* a2s = a1s + 32;

    const int h = blockIdx.y, b = blockIdx.z;
    const int n0 = blockIdx.x * 128;
    const int tid = threadIdx.x;

    for (int i = tid; i < FIN*ND; i += 256) {
        float w = W[h*FIN*ND + i];
        Ws2[i >> 5][i & 31] = pack2(w, w);
    }
    if (tid < 64) {
        float v = a[h*2*ND + tid];
        if (tid < 32) a1s[tid] = v; else a2s[tid-32] = v;
    }
    const float* src = g_xT + ((size_t)b*FIN)*NN + n0;
    for (int idx = tid; idx < FIN*32; idx += 256) {
        int k = idx >> 5, n4 = idx & 31;
        float4 v = *(const float4*)(src + (size_t)k*NN + 4*n4);
        *(float4*)&xTs[k][4*n4] = v;
    }
    __syncthreads();

    const int tx = tid & 7, ty = tid >> 3;   // tx: 4-col group, ty: 4-row group
    unsigned long long acc[4][2];
    #pragma unroll
    for (int j = 0; j < 4; j++) { acc[j][0] = 0ull; acc[j][1] = 0ull; }

    #pragma unroll 4
    for (int k = 0; k < FIN; k++) {
        ulonglong2 xp = *(const ulonglong2*)&xTs[k][4*ty];   // rows (4ty,4ty+1),(4ty+2,4ty+3)
        #pragma unroll
        for (int j = 0; j < 4; j++) {
            unsigned long long w2 = Ws2[k][4*tx + j];
            ffma2(acc[j][0], xp.x, w2);
            ffma2(acc[j][1], xp.y, w2);
        }
    }

    float ar[4][4];   // [row i][col j]
    #pragma unroll
    for (int j = 0; j < 4; j++) {
        float2 p0 = unpack2(acc[j][0]);
        float2 p1 = unpack2(acc[j][1]);
        ar[0][j] = p0.x; ar[1][j] = p0.y; ar[2][j] = p1.x; ar[3][j] = p1.y;
    }

    const int bh = b*NH + h;
    #pragma unroll
    for (int i = 0; i < 4; i++) {
        const int n = n0 + 4*ty + i;
        float4 o = make_float4(ar[i][0], ar[i][1], ar[i][2], ar[i][3]);
        *(float4*)&g_Wh[((size_t)(bh*NN + n))*ND + 4*tx] = o;

        float s1 = ar[i][0]*a1s[4*tx+0] + ar[i][1]*a1s[4*tx+1]
                 + ar[i][2]*a1s[4*tx+2] + ar[i][3]*a1s[4*tx+3];
        float s2 = ar[i][0]*a2s[4*tx+0] + ar[i][1]*a2s[4*tx+1]
                 + ar[i][2]*a2s[4*tx+2] + ar[i][3]*a2s[4*tx+3];
        #pragma unroll
        for (int o2 = 4; o2; o2 >>= 1) {
            s1 += __shfl_xor_sync(0xffffffffu, s1, o2);
            s2 += __shfl_xor_sync(0xffffffffu, s2, o2);
        }
        if (tx == 0) { g_Wh1[bh*NN + n] = s1; g_Wh2[bh*NN + n] = s2; }
    }
}

// ---------------- kernel 2: bitonic sort of packed (key|idx), one block per bh ----------------
__global__ void __launch_bounds__(1024) k2sort() {
    __shared__ unsigned long long kv[NN];
    const int bh = blockIdx.x;
    const int tid = threadIdx.x;

    for (int e = tid; e < NN; e += 1024) {
        unsigned u = __float_as_uint(g_Wh2[bh*NN + e]);
        u = (u & 0x80000000u) ? ~u : (u | 0x80000000u);
        kv[e] = ((unsigned long long)u << 32) | (unsigned)e;
    }
    __syncthreads();

    for (int k = 2; k <= NN; k <<= 1) {
        int s = k >> 1;
        for (; s >= 32; s >>= 1) {
            #pragma unroll
            for (int tt = 0; tt < 2; tt++) {
                int t = tid + tt*1024;
                int j = t ^ s;
                if (j > t) {
                    unsigned long long va = kv[t], vb = kv[j];
                    bool up = ((t & k) == 0);
                    if ((va > vb) == up) { kv[t] = vb; kv[j] = va; }
                }
            }
            __syncthreads();
        }
        for (; s >= 1; s >>= 1) {
            #pragma unroll
            for (int tt = 0; tt < 2; tt++) {
                int t = tid + tt*1024;
                int j = t ^ s;
                if (j > t) {
                    unsigned long long va = kv[t], vb = kv[j];
                    bool up = ((t & k) == 0);
                    if ((va > vb) == up) { kv[t] = vb; kv[j] = va; }
                }
            }
            __syncwarp();
        }
        __syncthreads();
    }

    for (int e = tid; e < NN; e += 1024) {
        unsigned long long v = kv[e];
        unsigned u = (unsigned)(v >> 32);
        u = (u & 0x80000000u) ? (u & 0x7fffffffu) : ~u;
        g_w2s [bh*NN + e] = __uint_as_float(u);
        g_perm[bh*NN + e] = (int)(v & 0xffffffffu);
    }
}

// ---------------- kernel 3: per-chunk local scans + chunk totals ----------------
__global__ void __launch_bounds__(1024) k3() {
    __shared__ float tA[CHSZ][ND+1];
    __shared__ float tB[CHSZ][ND+1];
    __shared__ float ewn[CHSZ], ewp[CHSZ];
    __shared__ int   pr[CHSZ];
    const int c = blockIdx.x, bh = blockIdx.y;
    const int tid = threadIdx.x, warp = tid >> 5, lane = tid & 31;
    const int base = bh*NN + c*CHSZ;

    if (tid < CHSZ) {
        float v = g_w2s[base + tid];
        ewn[tid] = expf(0.2f * v);
        ewp[tid] = expf(v);
        pr[tid]  = g_perm[base + tid];
    }
    __syncthreads();
    #pragma unroll
    for (int q = 0; q < 4; q++) {
        int r = warp + q*32;
        tA[r][lane] = g_Wh[((size_t)(bh*NN) + pr[r])*ND + lane];
    }
    __syncthreads();

    {
        float carry = 0.f;
        #pragma unroll
        for (int s = 0; s < 4; s++) {
            int j = s*32 + lane;
            float v = ewn[j] * tA[j][warp];
            float inc = warp_incl_scan(v, lane);
            float exc = __shfl_up_sync(0xffffffffu, inc, 1);
            if (lane == 0) exc = 0.f;
            tB[j][warp] = carry + exc;
            carry += __shfl_sync(0xffffffffu, inc, 31);
        }
        if (lane == 0) g_CnegT[(bh*NCH + c)*ND + warp] = carry;
    }
    __syncthreads();
    #pragma unroll
    for (int q = 0; q < 4; q++) {
        int r = warp + q*32;
        g_SnegL[((size_t)base + r)*ND + lane] = tB[r][lane];
    }
    __syncthreads();

    {
        float carry = 0.f;
        #pragma unroll
        for (int s = 3; s >= 0; s--) {
            int j = s*32 + (31 - lane);
            float v = ewp[j] * tA[j][warp];
            float inc = warp_incl_scan(v, lane);
            tB[j][warp] = carry + inc;
            carry += __shfl_sync(0xffffffffu, inc, 31);
        }
        if (lane == 0) g_CposT[(bh*NCH + c)*ND + warp] = carry;
    }
    __syncthreads();
    #pragma unroll
    for (int q = 0; q < 4; q++) {
        int r = warp + q*32;
        g_SposL[((size_t)base + r)*ND + lane] = tB[r][lane];
    }

    if (warp == 0) {
        float carry = 0.f;
        #pragma unroll
        for (int s = 0; s < 4; s++) {
            int j = s*32 + lane;
            float inc = warp_incl_scan(ewn[j], lane);
            float exc = __shfl_up_sync(0xffffffffu, inc, 1);
            if (lane == 0) exc = 0.f;
            g_pnL[base + j] = carry + exc;
            carry += __shfl_sync(0xffffffffu, inc, 31);
        }
        if (lane == 0) g_pnT[bh*NCH + c] = carry;
    } else if (warp == 1) {
        float carry = 0.f;
        #pragma unroll
        for (int s = 3; s >= 0; s--) {
            int j = s*32 + (31 - lane);
            float inc = warp_incl_scan(ewp[j], lane);
            g_ppL[base + j] = carry + inc;
            carry += __shfl_sync(0xffffffffu, inc, 31);
        }
        if (lane == 0) g_ppT[bh*NCH + c] = carry;
    }
}

// ---------------- kernel 5: fused offsets + search + combine (128 rows/block) ----------------
__global__ void __launch_bounds__(256) k5f(float* __restrict__ out) {
    __shared__ float keys[NN];
    __shared__ float cn[NCH*ND], cp[NCH*ND];
    __shared__ float OffN[(NCH+1)*ND], OffP[NCH*ND];
    __shared__ float opn[NCH+1], opp[NCH];
    __shared__ float tn[NCH], tp[NCH];
    const int seg = blockIdx.x, bh = blockIdx.y;
    const int b = bh >> 2, h = bh & 3;
    const int tid = threadIdx.x, warp = tid >> 5, lane = tid & 31;

    for (int j = tid; j < NN/4; j += 256)
        ((float4*)keys)[j] = ((const float4*)(g_w2s + bh*NN))[j];
    for (int j = tid; j < NCH*ND; j += 256) {
        cn[j] = g_CnegT[bh*NCH*ND + j];
        cp[j] = g_CposT[bh*NCH*ND + j];
    }
    if (tid < NCH) { tn[tid] = g_pnT[bh*NCH + tid]; tp[tid] = g_ppT[bh*NCH + tid]; }
    __syncthreads();
    if (warp == 0) {
        float s = 0.f;
        #pragma unroll
        for (int c = 0; c < NCH; c++) { OffN[c*ND + lane] = s; s += cn[c*ND + lane]; }
        OffN[NCH*ND + lane] = s;
    } else if (warp == 1) {
        float s = 0.f;
        #pragma unroll
        for (int c = NCH-1; c >= 0; c--) { OffP[c*ND + lane] = s; s += cp[c*ND + lane]; }
    } else if (tid == 64) {
        float s = 0.f;
        #pragma unroll
        for (int c = 0; c < NCH; c++) { opn[c] = s; s += tn[c]; }
        opn[NCH] = s;
    } else if (tid == 65) {
        float s = 0.f;
        #pragma unroll
        for (int c = NCH-1; c >= 0; c--) { opp[c] = s; s += tp[c]; }
    }
    __syncthreads();

    const int i0 = seg*128 + warp*16;
    int lo_l = 0; float f1_l = 0.f, f2_l = 0.f;
    if (lane < 16) {
        float w1 = g_Wh1[bh*NN + i0 + lane];
        float thr = -w1;
        int lo = 0, hi = NN;
        #pragma unroll
        for (int it = 0; it < 11; it++) {
            int mid = (lo + hi) >> 1;
            if (mid < hi) { if (keys[mid] <= thr) lo = mid + 1; else hi = mid; }
        }
        lo_l = lo;
        f1_l = expf(w1);
        f2_l = expf(0.2f * w1);
    }

    #pragma unroll 4
    for (int r = 0; r < 16; r++) {
        const int lo = __shfl_sync(0xffffffffu, lo_l, r);
        const float f1 = __shfl_sync(0xffffffffu, f1_l, r);
        const float f2 = __shfl_sync(0xffffffffu, f2_l, r);
        const int i = i0 + r;
        float sneg, spos, pn, pp;
        if (lo < NN) {
            const int c = lo >> 7;
            const size_t ix = ((size_t)(bh*NN) + lo)*ND + lane;
            sneg = g_SnegL[ix] + OffN[c*ND + lane];
            spos = g_SposL[ix] + OffP[c*ND + lane];
            pn   = g_pnL[bh*NN + lo] + opn[c];
            pp   = g_ppL[bh*NN + lo] + opp[c];
        } else {
            sneg = OffN[NCH*ND + lane];
            spos = 0.f;
            pn   = opn[NCH];
            pp   = 0.f;
        }
        float num = f2*sneg + f1*spos;
        float den = f2*pn + f1*pp;
        float hv = num / den;
        float res = hv > 0.f ? hv : expm1f(hv);
        out[((size_t)(b*NN + i))*(NH*ND) + h*ND + lane] = res;
    }
}

extern "C" void kernel_launch(void* const* d_in, const int* in_sizes, int n_in,
                              void* d_out, int out_size) {
    (void)in_sizes; (void)n_in; (void)out_size;
    const float* x = (const float*)d_in[0];
    const float* W = (const float*)d_in[1];
    const float* a = (const float*)d_in[2];
    float* out = (float*)d_out;

    static int smem_set = 0;
    if (!smem_set) {
        cudaFuncSetAttribute(k1, cudaFuncAttributeMaxDynamicSharedMemorySize, SM1_BYTES);
        smem_set = 1;
    }

    k0t<<<dim3(NN/32, FIN/32, NB), dim3(32, 8)>>>(x);
    k1<<<dim3(NN/128, NH, NB), 256, SM1_BYTES>>>(W, a);
    k2sort<<<BHD, 1024>>>();
    k3<<<dim3(NCH, BHD), 1024>>>();
    k5f<<<dim3(NN/128, BHD), 256>>>(out);
}

// round 6
// speedup vs baseline: 1.2203x; 1.2203x over previous
#include <cuda_runtime.h>

#define NB   4
#define NH   4
#define NN   2048
#define FIN  128
#define ND   32
#define BHD  (NB*NH)
#define NCH  16      // chunks per (b,h)
#define CHSZ 128     // rows per chunk

// scratch (device globals; no allocation allowed)
__device__ float  g_Wh  [BHD*NN*ND];
__device__ float  g_Wh1 [BHD*NN];
__device__ float  g_Wh2 [BHD*NN];
__device__ int    g_perm[BHD*NN];        // sorted pos -> original row
__device__ float  g_w2s [BHD*NN];        // sorted w2 keys
__device__ float  g_SnegL[BHD*NN*ND];    // per-chunk exclusive prefix of exp(.2 w2)*Wh
__device__ float  g_SposL[BHD*NN*ND];    // per-chunk inclusive suffix of exp(w2)*Wh
__device__ float  g_CnegT[BHD*NCH*ND];   // chunk total vectors
__device__ float  g_CposT[BHD*NCH*ND];
__device__ float  g_pnL[BHD*NN];         // scalar local prefix/suffix
__device__ float  g_ppL[BHD*NN];
__device__ float  g_pnT[BHD*NCH];        // scalar chunk totals
__device__ float  g_ppT[BHD*NCH];

__device__ __forceinline__ float warp_incl_scan(float v, int lane) {
    #pragma unroll
    for (int o = 1; o < 32; o <<= 1) {
        float u = __shfl_up_sync(0xffffffffu, v, o);
        if (lane >= o) v += u;
    }
    return v;
}

__device__ __forceinline__ unsigned long long pack2(float x, float y) {
    unsigned long long r;
    asm("mov.b64 %0, {%1, %2};" : "=l"(r) : "f"(x), "f"(y));
    return r;
}
__device__ __forceinline__ float2 unpack2(unsigned long long v) {
    float2 r;
    asm("mov.b64 {%0, %1}, %2;" : "=f"(r.x), "=f"(r.y) : "l"(v));
    return r;
}
__device__ __forceinline__ void ffma2(unsigned long long& d, unsigned long long a, unsigned long long b) {
    asm("fma.rn.f32x2 %0, %1, %2, %0;" : "+l"(d) : "l"(a), "l"(b));
}

// ---------------- kernel 1: Wh = x @ W[h] (in-block transpose + f32x2 register tile) ----
#define RS 132                               // xsT row stride (floats), mult of 4
#define SM1_X     (FIN*RS*4)                 // xsT[k][n]
#define SM1_W     (FIN*ND*4)                 // Ws[k][c]
#define SM1_BYTES (SM1_X + SM1_W + 256)

__global__ void __launch_bounds__(256) k1(const float* __restrict__ x,
                                          const float* __restrict__ W,
                                          const float* __restrict__ a) {
    extern __shared__ char sm1[];
    float* xsT = (float*)sm1;                       // [FIN][RS]
    float* Ws  = (float*)(sm1 + SM1_X);             // [FIN][ND]
    float* a1s = (float*)(sm1 + SM1_X + SM1_W);
    float* a2s = a1s + 32;

    const int h = blockIdx.y, b = blockIdx.z;
    const int n0 = blockIdx.x * 128;
    const int tid = threadIdx.x;

    for (int i = tid; i < FIN*ND; i += 256) Ws[i] = W[h*FIN*ND + i];
    if (tid < 64) {
        float v = a[h*2*ND + tid];
        if (tid < 32) a1s[tid] = v; else a2s[tid-32] = v;
    }

    // load + transpose x tile: thread -> row n = tid>>1, k-half = (tid&1)*64
    {
        const int n = tid >> 1, kh = (tid & 1) * 64;
        const float* xr = x + ((size_t)(b*NN + n0 + n))*FIN + kh;
        #pragma unroll
        for (int q = 0; q < 16; q++) {
            float4 v = ((const float4*)xr)[q];
            const int k = kh + 4*q;
            xsT[(k+0)*RS + n] = v.x;
            xsT[(k+1)*RS + n] = v.y;
            xsT[(k+2)*RS + n] = v.z;
            xsT[(k+3)*RS + n] = v.w;
        }
    }
    __syncthreads();

    const int tx = tid & 7, ty = tid >> 3;     // tx: 4-col group, ty: 4-row group
    const float* xp = xsT + 4*ty;
    const float* wp = Ws + 4*tx;

    unsigned long long acc[4][2];
    #pragma unroll
    for (int i = 0; i < 4; i++) { acc[i][0] = 0ull; acc[i][1] = 0ull; }

    #pragma unroll 8
    for (int k = 0; k < FIN; k++) {
        float4 xq = *(const float4*)(xp + (size_t)k*RS);        // 4 rows
        ulonglong2 wq = *(const ulonglong2*)(wp + k*ND);        // 4 cols (2 pairs)
        unsigned long long x0 = pack2(xq.x, xq.x);
        unsigned long long x1 = pack2(xq.y, xq.y);
        unsigned long long x2 = pack2(xq.z, xq.z);
        unsigned long long x3 = pack2(xq.w, xq.w);
        ffma2(acc[0][0], x0, wq.x); ffma2(acc[0][1], x0, wq.y);
        ffma2(acc[1][0], x1, wq.x); ffma2(acc[1][1], x1, wq.y);
        ffma2(acc[2][0], x2, wq.x); ffma2(acc[2][1], x2, wq.y);
        ffma2(acc[3][0], x3, wq.x); ffma2(acc[3][1], x3, wq.y);
    }

    const int bh = b*NH + h;
    #pragma unroll
    for (int i = 0; i < 4; i++) {
        float2 p0 = unpack2(acc[i][0]);   // cols 4tx+0, 4tx+1
        float2 p1 = unpack2(acc[i][1]);   // cols 4tx+2, 4tx+3
        const int n = n0 + 4*ty + i;
        *(float4*)&g_Wh[((size_t)(bh*NN + n))*ND + 4*tx] = make_float4(p0.x, p0.y, p1.x, p1.y);

        float s1 = p0.x*a1s[4*tx+0] + p0.y*a1s[4*tx+1] + p1.x*a1s[4*tx+2] + p1.y*a1s[4*tx+3];
        float s2 = p0.x*a2s[4*tx+0] + p0.y*a2s[4*tx+1] + p1.x*a2s[4*tx+2] + p1.y*a2s[4*tx+3];
        #pragma unroll
        for (int o2 = 4; o2; o2 >>= 1) {
            s1 += __shfl_xor_sync(0xffffffffu, s1, o2);
            s2 += __shfl_xor_sync(0xffffffffu, s2, o2);
        }
        if (tx == 0) { g_Wh1[bh*NN + n] = s1; g_Wh2[bh*NN + n] = s2; }
    }
}

// ---------------- kernel 2: bitonic sort of packed (key|idx), one block per bh ----------------
__global__ void __launch_bounds__(1024) k2sort() {
    __shared__ unsigned long long kv[NN];
    const int bh = blockIdx.x;
    const int tid = threadIdx.x;

    for (int e = tid; e < NN; e += 1024) {
        unsigned u = __float_as_uint(g_Wh2[bh*NN + e]);
        u = (u & 0x80000000u) ? ~u : (u | 0x80000000u);
        kv[e] = ((unsigned long long)u << 32) | (unsigned)e;
    }
    __syncthreads();

    for (int k = 2; k <= NN; k <<= 1) {
        int s = k >> 1;
        for (; s >= 32; s >>= 1) {
            #pragma unroll
            for (int tt = 0; tt < 2; tt++) {
                int t = tid + tt*1024;
                int j = t ^ s;
                if (j > t) {
                    unsigned long long va = kv[t], vb = kv[j];
                    bool up = ((t & k) == 0);
                    if ((va > vb) == up) { kv[t] = vb; kv[j] = va; }
                }
            }
            __syncthreads();
        }
        for (; s >= 1; s >>= 1) {
            #pragma unroll
            for (int tt = 0; tt < 2; tt++) {
                int t = tid + tt*1024;
                int j = t ^ s;
                if (j > t) {
                    unsigned long long va = kv[t], vb = kv[j];
                    bool up = ((t & k) == 0);
                    if ((va > vb) == up) { kv[t] = vb; kv[j] = va; }
                }
            }
            __syncwarp();
        }
        __syncthreads();
    }

    for (int e = tid; e < NN; e += 1024) {
        unsigned long long v = kv[e];
        unsigned u = (unsigned)(v >> 32);
        u = (u & 0x80000000u) ? (u & 0x7fffffffu) : ~u;
        g_w2s [bh*NN + e] = __uint_as_float(u);
        g_perm[bh*NN + e] = (int)(v & 0xffffffffu);
    }
}

// ---------------- kernel 3: per-chunk local scans + chunk totals (3 barriers) ----------------
#define SM3_T     (CHSZ*(ND+1)*4)
#define SM3_BYTES (3*SM3_T + CHSZ*4*2 + CHSZ*4)

__global__ void __launch_bounds__(1024) k3() {
    extern __shared__ char sm3[];
    float (*tA )[ND+1] = (float(*)[ND+1])sm3;
    float (*tBn)[ND+1] = (float(*)[ND+1])(sm3 + SM3_T);
    float (*tBp)[ND+1] = (float(*)[ND+1])(sm3 + 2*SM3_T);
    float* ewn = (float*)(sm3 + 3*SM3_T);
    float* ewp = ewn + CHSZ;
    int*   pr  = (int*)(ewp + CHSZ);

    const int c = blockIdx.x, bh = blockIdx.y;
    const int tid = threadIdx.x, warp = tid >> 5, lane = tid & 31;
    const int base = bh*NN + c*CHSZ;

    if (tid < CHSZ) {
        float v = g_w2s[base + tid];
        ewn[tid] = expf(0.2f * v);
        ewp[tid] = expf(v);
        pr[tid]  = g_perm[base + tid];
    }
    __syncthreads();
    #pragma unroll
    for (int q = 0; q < 4; q++) {
        int r = warp + q*32;
        tA[r][lane] = g_Wh[((size_t)(bh*NN) + pr[r])*ND + lane];
    }
    __syncthreads();

    // forward neg scan (exclusive), warp = channel
    {
        float carry = 0.f;
        #pragma unroll
        for (int s = 0; s < 4; s++) {
            int j = s*32 + lane;
            float v = ewn[j] * tA[j][warp];
            float inc = warp_incl_scan(v, lane);
            float exc = __shfl_up_sync(0xffffffffu, inc, 1);
            if (lane == 0) exc = 0.f;
            tBn[j][warp] = carry + exc;
            carry += __shfl_sync(0xffffffffu, inc, 31);
        }
        if (lane == 0) g_CnegT[(bh*NCH + c)*ND + warp] = carry;
    }
    // backward pos scan (inclusive suffix) — independent of the neg scan
    {
        float carry = 0.f;
        #pragma unroll
        for (int s = 3; s >= 0; s--) {
            int j = s*32 + (31 - lane);
            float v = ewp[j] * tA[j][warp];
            float inc = warp_incl_scan(v, lane);
            tBp[j][warp] = carry + inc;
            carry += __shfl_sync(0xffffffffu, inc, 31);
        }
        if (lane == 0) g_CposT[(bh*NCH + c)*ND + warp] = carry;
    }
    // scalar scans (warps 0 and 1), straight to global
    if (warp == 0) {
        float carry = 0.f;
        #pragma unroll
        for (int s = 0; s < 4; s++) {
            int j = s*32 + lane;
            float inc = warp_incl_scan(ewn[j], lane);
            float exc = __shfl_up_sync(0xffffffffu, inc, 1);
            if (lane == 0) exc = 0.f;
            g_pnL[base + j] = carry + exc;
            carry += __shfl_sync(0xffffffffu, inc, 31);
        }
        if (lane == 0) g_pnT[bh*NCH + c] = carry;
    } else if (warp == 1) {
        float carry = 0.f;
        #pragma unroll
        for (int s = 3; s >= 0; s--) {
            int j = s*32 + (31 - lane);
            float inc = warp_incl_scan(ewp[j], lane);
            g_ppL[base + j] = carry + inc;
            carry += __shfl_sync(0xffffffffu, inc, 31);
        }
        if (lane == 0) g_ppT[bh*NCH + c] = carry;
    }
    __syncthreads();
    #pragma unroll
    for (int q = 0; q < 4; q++) {
        int r = warp + q*32;
        g_SnegL[((size_t)base + r)*ND + lane] = tBn[r][lane];
        g_SposL[((size_t)base + r)*ND + lane] = tBp[r][lane];
    }
}

// ---------------- kernel 5: fused offsets + search + combine (128 rows/block) ----------------
__global__ void __launch_bounds__(256) k5f(float* __restrict__ out) {
    __shared__ float keys[NN];
    __shared__ float cn[NCH*ND], cp[NCH*ND];
    __shared__ float OffN[(NCH+1)*ND], OffP[NCH*ND];
    __shared__ float opn[NCH+1], opp[NCH];
    __shared__ float tn[NCH], tp[NCH];
    const int seg = blockIdx.x, bh = blockIdx.y;
    const int b = bh >> 2, h = bh & 3;
    const int tid = threadIdx.x, warp = tid >> 5, lane = tid & 31;

    for (int j = tid; j < NN/4; j += 256)
        ((float4*)keys)[j] = ((const float4*)(g_w2s + bh*NN))[j];
    for (int j = tid; j < NCH*ND; j += 256) {
        cn[j] = g_CnegT[bh*NCH*ND + j];
        cp[j] = g_CposT[bh*NCH*ND + j];
    }
    if (tid < NCH) { tn[tid] = g_pnT[bh*NCH + tid]; tp[tid] = g_ppT[bh*NCH + tid]; }
    __syncthreads();
    if (warp == 0) {
        float s = 0.f;
        #pragma unroll
        for (int c = 0; c < NCH; c++) { OffN[c*ND + lane] = s; s += cn[c*ND + lane]; }
        OffN[NCH*ND + lane] = s;
    } else if (warp == 1) {
        float s = 0.f;
        #pragma unroll
        for (int c = NCH-1; c >= 0; c--) { OffP[c*ND + lane] = s; s += cp[c*ND + lane]; }
    } else if (tid == 64) {
        float s = 0.f;
        #pragma unroll
        for (int c = 0; c < NCH; c++) { opn[c] = s; s += tn[c]; }
        opn[NCH] = s;
    } else if (tid == 65) {
        float s = 0.f;
        #pragma unroll
        for (int c = NCH-1; c >= 0; c--) { opp[c] = s; s += tp[c]; }
    }
    __syncthreads();

    const int i0 = seg*128 + warp*16;
    int lo_l = 0; float f1_l = 0.f, f2_l = 0.f;
    if (lane < 16) {
        float w1 = g_Wh1[bh*NN + i0 + lane];
        float thr = -w1;
        int lo = 0, hi = NN;
        #pragma unroll
        for (int it = 0; it < 11; it++) {
            int mid = (lo + hi) >> 1;
            if (mid < hi) { if (keys[mid] <= thr) lo = mid + 1; else hi = mid; }
        }
        lo_l = lo;
        f1_l = expf(w1);
        f2_l = expf(0.2f * w1);
    }

    #pragma unroll 4
    for (int r = 0; r < 16; r++) {
        const int lo = __shfl_sync(0xffffffffu, lo_l, r);
        const float f1 = __shfl_sync(0xffffffffu, f1_l, r);
        const float f2 = __shfl_sync(0xffffffffu, f2_l, r);
        const int i = i0 + r;
        float sneg, spos, pn, pp;
        if (lo < NN) {
            const int c = lo >> 7;
            const size_t ix = ((size_t)(bh*NN) + lo)*ND + lane;
            sneg = g_SnegL[ix] + OffN[c*ND + lane];
            spos = g_SposL[ix] + OffP[c*ND + lane];
            pn   = g_pnL[bh*NN + lo] + opn[c];
            pp   = g_ppL[bh*NN + lo] + opp[c];
        } else {
            sneg = OffN[NCH*ND + lane];
            spos = 0.f;
            pn   = opn[NCH];
            pp   = 0.f;
        }
        float num = f2*sneg + f1*spos;
        float den = f2*pn + f1*pp;
        float hv = num / den;
        float res = hv > 0.f ? hv : expm1f(hv);
        out[((size_t)(b*NN + i))*(NH*ND) + h*ND + lane] = res;
    }
}

extern "C" void kernel_launch(void* const* d_in, const int* in_sizes, int n_in,
                              void* d_out, int out_size) {
    (void)in_sizes; (void)n_in; (void)out_size;
    const float* x = (const float*)d_in[0];
    const float* W = (const float*)d_in[1];
    const float* a = (const float*)d_in[2];
    float* out = (float*)d_out;

    static int attr_set = 0;
    if (!attr_set) {
        cudaFuncSetAttribute(k1, cudaFuncAttributeMaxDynamicSharedMemorySize, SM1_BYTES);
        cudaFuncSetAttribute(k3, cudaFuncAttributeMaxDynamicSharedMemorySize, SM3_BYTES);
        attr_set = 1;
    }

    k1<<<dim3(NN/128, NH, NB), 256, SM1_BYTES>>>(x, W, a);
    k2sort<<<BHD, 1024>>>();
    k3<<<dim3(NCH, BHD), 1024, SM3_BYTES>>>();
    k5f<<<dim3(NN/128, BHD), 256>>>(out);
}